// round 14
// baseline (speedup 1.0000x reference)
#include <cuda_runtime.h>
#include <cooperative_groups.h>
#include <cstdint>

namespace cg = cooperative_groups;

// out[n,64] = sum over edges e with dst[e]==n of x[src[e],:] * w[e]
// Inputs: x (float32, N*64), edge_index ((2,E), int64-or-int32), edge_weight (float32, E)
//
// Single cooperative kernel, three phases separated by grid.sync():
//   phase 1: zero per-node counters + overflow tail, probe index dtype
//   phase 2: fill — bucket each edge by dst ({src,w} 8B record); overflow -> list
//   phase 3: gather — 16 threads/node, atomic-free accumulate, plain STG per row;
//            inline overflow-list scan (tail ~always 0)
// One launch instead of three: removes ~4.5us/launch fixed overhead measured
// on the (nearly empty) init and fixup kernels in rounds 9-13.

static constexpr int D    = 64;       // feature dim
static constexpr int TPB  = 256;
static constexpr int MAXN = 100352;   // >= N (problem: 100000), multiple of 4
static constexpr int CAP  = 32;       // bucket slots/node (P(deg>32) ~ 3e-7/node)
static constexpr int OVFC = 1250000;  // overflow capacity >= E (worst case)

// ---- device scratch (static globals: sanctioned no-alloc scratch) ----
__device__ int g_idx_is64;
__device__ int g_ovf_tail;
__device__ __align__(16) int g_count[MAXN];                   // per-node counters
__device__ unsigned long long g_bucket[(size_t)MAXN * CAP];   // {src, w} records
__device__ unsigned long long g_ovf_rec[OVFC];                // overflow {src, w}
__device__ int g_ovf_dst[OVFC];                               // overflow dst

__global__ __launch_bounds__(TPB)
void mp_fused_kernel(const float* __restrict__ x,
                     const void* __restrict__ edge_index,
                     const float* __restrict__ w,
                     float* __restrict__ out,
                     int E, int N) {
    cg::grid_group grid = cg::this_grid();
    const int tid      = blockIdx.x * blockDim.x + threadIdx.x;
    const int nthreads = gridDim.x * blockDim.x;

    // ---- Phase 1: probe dtype (block 0) + zero counters (all blocks) ----
    // int64 indices < 2^31 => every odd 32-bit word is zero; int32 indices
    // are random node ids, so all-zero over 1024 samples has prob ~1e-5024.
    if (blockIdx.x == 0) {
        __shared__ int any_nonzero;
        if (threadIdx.x == 0) any_nonzero = 0;
        __syncthreads();
        const int* ei32 = (const int*)edge_index;
        int n = E < 1024 ? E : 1024;
        for (int k = threadIdx.x; k < n; k += blockDim.x)
            if (ei32[2 * k + 1] != 0) any_nonzero = 1;
        __syncthreads();
        if (threadIdx.x == 0) {
            g_idx_is64 = (any_nonzero == 0) ? 1 : 0;
            g_ovf_tail = 0;
        }
    }
    for (int i = tid; i < MAXN / 4; i += nthreads)
        reinterpret_cast<int4*>(g_count)[i] = make_int4(0, 0, 0, 0);

    grid.sync();

    // ---- Phase 2: fill — bucket every edge by dst ----
    {
        const int is64 = g_idx_is64;   // uniform
        for (int e = tid; e < E; e += nthreads) {
            int s, d;
            if (is64) {
                const long long* p = (const long long*)edge_index;
                s = (int)__ldg(p + e);
                d = (int)__ldg(p + E + e);
            } else {
                const int* p = (const int*)edge_index;
                s = __ldg(p + e);
                d = __ldg(p + E + e);
            }
            float wt = __ldg(w + e);

            unsigned long long rec = (unsigned long long)(unsigned)s
                                   | ((unsigned long long)__float_as_uint(wt) << 32);
            int slot = atomicAdd(&g_count[d], 1);
            if (slot < CAP) {
                g_bucket[(size_t)d * CAP + slot] = rec;
            } else {
                // Overflow (expected ~never): append; applied inline in gather.
                int idx = atomicAdd(&g_ovf_tail, 1);
                if (idx < OVFC) {
                    g_ovf_rec[idx] = rec;
                    g_ovf_dst[idx] = d;
                }
            }
        }
    }

    grid.sync();

    // ---- Phase 3: gather — 16 threads/node, atomic-free, STG.128 per lane ----
    // nthreads is a multiple of 16, so lane stays fixed across the stride.
    const int total = N * 16;
    for (int idx = tid; idx < total; idx += nthreads) {
        int node = idx >> 4;
        int lane = idx & 15;

        int deg = g_count[node];
        if (deg > CAP) deg = CAP;
        const unsigned long long* buf = g_bucket + (size_t)node * CAP;

        float4 a0 = make_float4(0.f, 0.f, 0.f, 0.f);
        float4 a1 = make_float4(0.f, 0.f, 0.f, 0.f);
        float4 a2 = make_float4(0.f, 0.f, 0.f, 0.f);
        float4 a3 = make_float4(0.f, 0.f, 0.f, 0.f);

        int i = 0;
        for (; i + 4 <= deg; i += 4) {
            unsigned long long r0 = buf[i + 0];
            unsigned long long r1 = buf[i + 1];
            unsigned long long r2 = buf[i + 2];
            unsigned long long r3 = buf[i + 3];
            // 4 independent row gathers in flight
            float4 v0 = __ldg(reinterpret_cast<const float4*>(x + (size_t)(unsigned)(r0 & 0xffffffffu) * D) + lane);
            float4 v1 = __ldg(reinterpret_cast<const float4*>(x + (size_t)(unsigned)(r1 & 0xffffffffu) * D) + lane);
            float4 v2 = __ldg(reinterpret_cast<const float4*>(x + (size_t)(unsigned)(r2 & 0xffffffffu) * D) + lane);
            float4 v3 = __ldg(reinterpret_cast<const float4*>(x + (size_t)(unsigned)(r3 & 0xffffffffu) * D) + lane);
            float w0 = __uint_as_float((unsigned)(r0 >> 32));
            float w1 = __uint_as_float((unsigned)(r1 >> 32));
            float w2 = __uint_as_float((unsigned)(r2 >> 32));
            float w3 = __uint_as_float((unsigned)(r3 >> 32));
            a0.x += v0.x * w0; a0.y += v0.y * w0; a0.z += v0.z * w0; a0.w += v0.w * w0;
            a1.x += v1.x * w1; a1.y += v1.y * w1; a1.z += v1.z * w1; a1.w += v1.w * w1;
            a2.x += v2.x * w2; a2.y += v2.y * w2; a2.z += v2.z * w2; a2.w += v2.w * w2;
            a3.x += v3.x * w3; a3.y += v3.y * w3; a3.z += v3.z * w3; a3.w += v3.w * w3;
        }
        for (; i < deg; i++) {
            unsigned long long r = buf[i];
            float4 v = __ldg(reinterpret_cast<const float4*>(x + (size_t)(unsigned)(r & 0xffffffffu) * D) + lane);
            float wt = __uint_as_float((unsigned)(r >> 32));
            a0.x += v.x * wt; a0.y += v.y * wt; a0.z += v.z * wt; a0.w += v.w * wt;
        }

        // Inline overflow handling (tail is ~always 0; uniform branch).
        int tail = g_ovf_tail;
        if (tail > 0) {
            if (tail > OVFC) tail = OVFC;
            for (int e = 0; e < tail; e++) {
                if (g_ovf_dst[e] == node) {
                    unsigned long long r = g_ovf_rec[e];
                    float4 v = __ldg(reinterpret_cast<const float4*>(
                        x + (size_t)(unsigned)(r & 0xffffffffu) * D) + lane);
                    float wt = __uint_as_float((unsigned)(r >> 32));
                    a0.x += v.x * wt; a0.y += v.y * wt;
                    a0.z += v.z * wt; a0.w += v.w * wt;
                }
            }
        }

        float4 r;
        r.x = (a0.x + a1.x) + (a2.x + a3.x);
        r.y = (a0.y + a1.y) + (a2.y + a3.y);
        r.z = (a0.z + a1.z) + (a2.z + a3.z);
        r.w = (a0.w + a1.w) + (a2.w + a3.w);

        *(reinterpret_cast<float4*>(out + (size_t)node * D) + lane) = r;
    }
}

extern "C" void kernel_launch(void* const* d_in, const int* in_sizes, int n_in,
                              void* d_out, int out_size) {
    const float* x   = (const float*)d_in[0];
    const void*  ei  = d_in[1];
    const float* w   = (const float*)d_in[2];
    float*       out = (float*)d_out;

    int E = in_sizes[1] / 2;       // edge_index is (2, E)
    int N = out_size / D;          // number of nodes

    // Deterministic grid sizing for cooperative launch (no allocation).
    int numSMs = 0;
    cudaDeviceGetAttribute(&numSMs, cudaDevAttrMultiProcessorCount, 0);
    int blocksPerSM = 0;
    cudaOccupancyMaxActiveBlocksPerMultiprocessor(&blocksPerSM,
                                                  (const void*)mp_fused_kernel,
                                                  TPB, 0);
    if (numSMs <= 0) numSMs = 1;
    if (blocksPerSM <= 0) blocksPerSM = 1;
    long long needed = ((long long)N * 16 + TPB - 1) / TPB;
    long long cap = (long long)numSMs * blocksPerSM;
    int blocks = (int)(needed < cap ? needed : cap);
    if (blocks < 1) blocks = 1;

    void* args[] = { (void*)&x, (void*)&ei, (void*)&w, (void*)&out,
                     (void*)&E, (void*)&N };
    cudaLaunchCooperativeKernel((const void*)mp_fused_kernel,
                                dim3(blocks), dim3(TPB), args, 0, (cudaStream_t)0);
}

// round 15
// speedup vs baseline: 1.2934x; 1.2934x over previous
#include <cuda_runtime.h>
#include <cstdint>

// out[n,64] = sum over edges e with dst[e]==n of x[src[e],:] * w[e]
// Inputs: x (float32, N*64), edge_index ((2,E), int64-or-int32), edge_weight (float32, E)
//
// Bucketed CSR-lite, 1 memset + 2 kernels:
//   memset: zero per-node counters AND the overflow tail (stored at g_count[N])
//   fill  : per-warp dtype probe (ballot on odd words) + bucket each edge by dst
//   gather: 16 threads/node, atomic-free accumulate, plain STG per row;
//           inline overflow-list scan (tail ~always 0)

static constexpr int D    = 64;       // feature dim
static constexpr int TPB  = 256;
static constexpr int MAXN = 100352;   // > N (problem: 100000); slot N holds ovf tail
static constexpr int CAP  = 32;       // bucket slots/node (P(deg>32) ~ 3e-7/node)
static constexpr int OVFC = 1250000;  // overflow capacity >= E (worst case)

// ---- device scratch (static globals: sanctioned no-alloc scratch) ----
__device__ __align__(16) int g_count[MAXN];                   // [0,N): counters, [N]: ovf tail
__device__ unsigned long long g_bucket[(size_t)MAXN * CAP];   // {src, w} records
__device__ unsigned long long g_ovf_rec[OVFC];                // overflow {src, w}
__device__ int g_ovf_dst[OVFC];                               // overflow dst

// ---- 1) fill: bucket every edge by dst; warp-level dtype probe ----
// int64 indices < 2^31 => every odd 32-bit word is zero. For int32 data the
// odd words are random node ids (zero w.p. 1e-5), so a full warp of zeros has
// probability 1e-160 — the ballot is deterministic in practice & warp-uniform.
__global__ __launch_bounds__(TPB)
void fill_kernel(const void* __restrict__ edge_index,
                 const float* __restrict__ w,
                 int E, int N) {
    int e = blockIdx.x * blockDim.x + threadIdx.x;
    int ec = e < E ? e : (E - 1);

    const int* ei32 = (const int*)edge_index;
    int odd = __ldg(ei32 + 2 * ec + 1);
    bool is64 = __all_sync(0xffffffffu, odd == 0);   // warp-uniform

    if (e >= E) return;

    int s, d;
    if (is64) {
        const long long* p = (const long long*)edge_index;
        s = (int)__ldg(p + e);
        d = (int)__ldg(p + E + e);
    } else {
        s = __ldg(ei32 + e);
        d = __ldg(ei32 + E + e);
    }
    float wt = __ldg(w + e);

    unsigned long long rec = (unsigned long long)(unsigned)s
                           | ((unsigned long long)__float_as_uint(wt) << 32);
    int slot = atomicAdd(&g_count[d], 1);
    if (slot < CAP) {
        g_bucket[(size_t)d * CAP + slot] = rec;
    } else {
        // Overflow (expected ~never): append to list, applied inline in gather.
        int idx = atomicAdd(&g_count[N], 1);         // tail lives at g_count[N]
        if (idx < OVFC) {
            g_ovf_rec[idx] = rec;
            g_ovf_dst[idx] = d;
        }
    }
}

// ---- 2) gather: 16 threads/node, atomic-free, one STG.128 per lane ----
__global__ __launch_bounds__(TPB)
void gather_kernel(const float* __restrict__ x,
                   float* __restrict__ out,
                   int N) {
    int gid  = blockIdx.x * blockDim.x + threadIdx.x;
    int node = gid >> 4;
    int lane = gid & 15;
    if (node >= N) return;

    int deg = g_count[node];
    if (deg > CAP) deg = CAP;
    const unsigned long long* buf = g_bucket + (size_t)node * CAP;

    float4 a0 = make_float4(0.f, 0.f, 0.f, 0.f);
    float4 a1 = make_float4(0.f, 0.f, 0.f, 0.f);
    float4 a2 = make_float4(0.f, 0.f, 0.f, 0.f);
    float4 a3 = make_float4(0.f, 0.f, 0.f, 0.f);

    int i = 0;
    for (; i + 4 <= deg; i += 4) {
        unsigned long long r0 = buf[i + 0];
        unsigned long long r1 = buf[i + 1];
        unsigned long long r2 = buf[i + 2];
        unsigned long long r3 = buf[i + 3];
        // 4 independent row gathers in flight
        float4 v0 = __ldg(reinterpret_cast<const float4*>(x + (size_t)(unsigned)(r0 & 0xffffffffu) * D) + lane);
        float4 v1 = __ldg(reinterpret_cast<const float4*>(x + (size_t)(unsigned)(r1 & 0xffffffffu) * D) + lane);
        float4 v2 = __ldg(reinterpret_cast<const float4*>(x + (size_t)(unsigned)(r2 & 0xffffffffu) * D) + lane);
        float4 v3 = __ldg(reinterpret_cast<const float4*>(x + (size_t)(unsigned)(r3 & 0xffffffffu) * D) + lane);
        float w0 = __uint_as_float((unsigned)(r0 >> 32));
        float w1 = __uint_as_float((unsigned)(r1 >> 32));
        float w2 = __uint_as_float((unsigned)(r2 >> 32));
        float w3 = __uint_as_float((unsigned)(r3 >> 32));
        a0.x += v0.x * w0; a0.y += v0.y * w0; a0.z += v0.z * w0; a0.w += v0.w * w0;
        a1.x += v1.x * w1; a1.y += v1.y * w1; a1.z += v1.z * w1; a1.w += v1.w * w1;
        a2.x += v2.x * w2; a2.y += v2.y * w2; a2.z += v2.z * w2; a2.w += v2.w * w2;
        a3.x += v3.x * w3; a3.y += v3.y * w3; a3.z += v3.z * w3; a3.w += v3.w * w3;
    }
    for (; i < deg; i++) {
        unsigned long long r = buf[i];
        float4 v = __ldg(reinterpret_cast<const float4*>(x + (size_t)(unsigned)(r & 0xffffffffu) * D) + lane);
        float wt = __uint_as_float((unsigned)(r >> 32));
        a0.x += v.x * wt; a0.y += v.y * wt; a0.z += v.z * wt; a0.w += v.w * wt;
    }

    // Inline overflow handling (tail is ~always 0; uniform branch).
    int tail = g_count[N];
    if (tail > 0) {
        if (tail > OVFC) tail = OVFC;
        for (int e = 0; e < tail; e++) {
            if (g_ovf_dst[e] == node) {
                unsigned long long r = g_ovf_rec[e];
                float4 v = __ldg(reinterpret_cast<const float4*>(
                    x + (size_t)(unsigned)(r & 0xffffffffu) * D) + lane);
                float wt = __uint_as_float((unsigned)(r >> 32));
                a0.x += v.x * wt; a0.y += v.y * wt;
                a0.z += v.z * wt; a0.w += v.w * wt;
            }
        }
    }

    float4 r;
    r.x = (a0.x + a1.x) + (a2.x + a3.x);
    r.y = (a0.y + a1.y) + (a2.y + a3.y);
    r.z = (a0.z + a1.z) + (a2.z + a3.z);
    r.w = (a0.w + a1.w) + (a2.w + a3.w);

    *(reinterpret_cast<float4*>(out + (size_t)node * D) + lane) = r;
}

extern "C" void kernel_launch(void* const* d_in, const int* in_sizes, int n_in,
                              void* d_out, int out_size) {
    const float* x   = (const float*)d_in[0];
    const void*  ei  = d_in[1];
    const float* w   = (const float*)d_in[2];
    float*       out = (float*)d_out;

    const int E = in_sizes[1] / 2;       // edge_index is (2, E)
    const int N = out_size / D;          // number of nodes

    // 1) zero counters [0,N] (includes overflow tail at slot N) via memset node
    {
        void* cnt_ptr = nullptr;
        cudaGetSymbolAddress(&cnt_ptr, g_count);
        cudaMemsetAsync(cnt_ptr, 0, (size_t)(N + 1) * sizeof(int), (cudaStream_t)0);
    }
    // 2) bucket edges by dst (self-probing dtype via warp ballot)
    {
        int blocks = (E + TPB - 1) / TPB;
        fill_kernel<<<blocks, TPB>>>(ei, w, E, N);
    }
    // 3) atomic-free gather/accumulate/store (handles overflow inline)
    {
        long long total = (long long)N * 16;
        int blocks = (int)((total + TPB - 1) / TPB);
        gather_kernel<<<blocks, TPB>>>(x, out, N);
    }
}

// round 16
// speedup vs baseline: 1.3244x; 1.0240x over previous
#include <cuda_runtime.h>
#include <cstdint>

// out[n,64] = sum over edges e with dst[e]==n of x[src[e],:] * w[e]
// Inputs: x (float32, N*64), edge_index ((2,E), int64-or-int32), edge_weight (float32, E)
//
// Bucketed CSR-lite (R13 init/fill; latency-optimized gather):
//   init  : zero per-node counters (int4) + overflow tail, probe index dtype
//   fill  : bucket each edge by dst ({src,w} 8B record); overflow -> list
//   gather: 16 threads/node; software-pipelined record prefetch, predicated
//           4-wide tail (masked lanes re-read the same row: no extra traffic),
//           shift-based addressing; plain STG.128 per lane.

static constexpr int D    = 64;       // feature dim
static constexpr int TPB  = 256;
static constexpr int MAXN = 100352;   // >= N (problem: 100000), multiple of 4
static constexpr int CAP  = 32;       // bucket slots/node (P(deg>32) ~ 3e-7/node)
static constexpr int OVFC = 1250000;  // overflow capacity >= E (worst case)

// ---- device scratch (static globals: sanctioned no-alloc scratch) ----
__device__ int g_idx_is64;
__device__ int g_ovf_tail;
__device__ __align__(16) int g_count[MAXN];                   // per-node counters
__device__ __align__(16) unsigned long long g_bucket[(size_t)MAXN * CAP];
__device__ unsigned long long g_ovf_rec[OVFC];                // overflow {src, w}
__device__ int g_ovf_dst[OVFC];                               // overflow dst

// ---- 1) init: zero counters (int4) + overflow tail, probe index dtype ----
// int64 indices < 2^31 => every odd 32-bit word is zero; int32 indices are
// random node ids, so all-zero over 1024 samples has probability ~1e-5024.
__global__ void init_kernel(const int* __restrict__ ei32, int E) {
    int i = blockIdx.x * blockDim.x + threadIdx.x;
    if (blockIdx.x == 0) {
        __shared__ int any_nonzero;
        if (threadIdx.x == 0) any_nonzero = 0;
        __syncthreads();
        int n = E < 1024 ? E : 1024;
        for (int k = threadIdx.x; k < n; k += blockDim.x)
            if (ei32[2 * k + 1] != 0) any_nonzero = 1;
        __syncthreads();
        if (threadIdx.x == 0) {
            g_idx_is64 = (any_nonzero == 0) ? 1 : 0;
            g_ovf_tail = 0;
        }
    }
    if (i < MAXN / 4)
        reinterpret_cast<int4*>(g_count)[i] = make_int4(0, 0, 0, 0);
}

// ---- 2) fill: bucket every edge by dst ----
__global__ __launch_bounds__(TPB)
void fill_kernel(const void* __restrict__ edge_index,
                 const float* __restrict__ w,
                 int E) {
    int e = blockIdx.x * blockDim.x + threadIdx.x;
    if (e >= E) return;

    int s, d;
    if (g_idx_is64) {
        const long long* p = (const long long*)edge_index;
        s = (int)__ldg(p + e);
        d = (int)__ldg(p + E + e);
    } else {
        const int* p = (const int*)edge_index;
        s = __ldg(p + e);
        d = __ldg(p + E + e);
    }
    float wt = __ldg(w + e);

    unsigned long long rec = (unsigned long long)(unsigned)s
                           | ((unsigned long long)__float_as_uint(wt) << 32);
    int slot = atomicAdd(&g_count[d], 1);
    if (slot < CAP) {
        g_bucket[(size_t)d * CAP + slot] = rec;
    } else {
        // Overflow (expected ~never): append to list, applied inline in gather.
        int idx = atomicAdd(&g_ovf_tail, 1);
        if (idx < OVFC) {
            g_ovf_rec[idx] = rec;
            g_ovf_dst[idx] = d;
        }
    }
}

// ---- 3) gather: 16 threads/node, atomic-free, one STG.128 per lane ----
__global__ __launch_bounds__(TPB)
void gather_kernel(const float* __restrict__ x,
                   float* __restrict__ out,
                   int N) {
    int gid  = blockIdx.x * blockDim.x + threadIdx.x;
    int node = gid >> 4;
    int lane = gid & 15;
    if (node >= N) return;

    int deg = g_count[node];
    if (deg > CAP) deg = CAP;
    const ulonglong2* p2 =
        reinterpret_cast<const ulonglong2*>(g_bucket + (size_t)node * CAP);
    // Row address = xlane + (src << 8): one shift+add, no 64-bit MUL.
    const char* xlane = (const char*)x + (lane << 4);

    float4 a0 = make_float4(0.f, 0.f, 0.f, 0.f);
    float4 a1 = make_float4(0.f, 0.f, 0.f, 0.f);
    float4 a2 = make_float4(0.f, 0.f, 0.f, 0.f);
    float4 a3 = make_float4(0.f, 0.f, 0.f, 0.f);

    int quads = deg >> 2;
    ulonglong2 ra, rb;
    if (quads > 0) { ra = __ldg(p2); rb = __ldg(p2 + 1); }
    for (int q = 0; q < quads; q++) {
        // Prefetch next quad's records while this quad's gathers fly.
        ulonglong2 na = ra, nb = rb;
        if (q + 1 < quads) {
            na = __ldg(p2 + 2 * (q + 1));
            nb = __ldg(p2 + 2 * (q + 1) + 1);
        }
        unsigned s0 = (unsigned)ra.x, s1 = (unsigned)ra.y;
        unsigned s2 = (unsigned)rb.x, s3 = (unsigned)rb.y;
        float w0 = __uint_as_float((unsigned)(ra.x >> 32));
        float w1 = __uint_as_float((unsigned)(ra.y >> 32));
        float w2 = __uint_as_float((unsigned)(rb.x >> 32));
        float w3 = __uint_as_float((unsigned)(rb.y >> 32));

        float4 v0 = __ldg((const float4*)(xlane + ((size_t)(s0 << 8))));
        float4 v1 = __ldg((const float4*)(xlane + ((size_t)(s1 << 8))));
        float4 v2 = __ldg((const float4*)(xlane + ((size_t)(s2 << 8))));
        float4 v3 = __ldg((const float4*)(xlane + ((size_t)(s3 << 8))));

        a0.x += v0.x * w0; a0.y += v0.y * w0; a0.z += v0.z * w0; a0.w += v0.w * w0;
        a1.x += v1.x * w1; a1.y += v1.y * w1; a1.z += v1.z * w1; a1.w += v1.w * w1;
        a2.x += v2.x * w2; a2.y += v2.y * w2; a2.z += v2.z * w2; a2.w += v2.w * w2;
        a3.x += v3.x * w3; a3.y += v3.y * w3; a3.z += v3.z * w3; a3.w += v3.w * w3;

        ra = na; rb = nb;
    }

    // Predicated tail (rem in {1,2,3}): masked lanes re-gather the first tail
    // row with weight 0 — identical cache lines, zero extra L2 traffic, and
    // no serial 1-wide dependent loop. Stale slots hold valid src ids.
    int rem = deg & 3;
    if (rem) {
        ulonglong2 ta = __ldg(p2 + 2 * quads);
        ulonglong2 tb = __ldg(p2 + 2 * quads + 1);
        unsigned s0 = (unsigned)ta.x;
        float    w0 = __uint_as_float((unsigned)(ta.x >> 32));
        unsigned s1 = (rem > 1) ? (unsigned)ta.y : s0;
        float    w1 = (rem > 1) ? __uint_as_float((unsigned)(ta.y >> 32)) : 0.f;
        unsigned s2 = (rem > 2) ? (unsigned)tb.x : s0;
        float    w2 = (rem > 2) ? __uint_as_float((unsigned)(tb.x >> 32)) : 0.f;

        float4 v0 = __ldg((const float4*)(xlane + ((size_t)(s0 << 8))));
        float4 v1 = __ldg((const float4*)(xlane + ((size_t)(s1 << 8))));
        float4 v2 = __ldg((const float4*)(xlane + ((size_t)(s2 << 8))));

        a0.x += v0.x * w0; a0.y += v0.y * w0; a0.z += v0.z * w0; a0.w += v0.w * w0;
        a1.x += v1.x * w1; a1.y += v1.y * w1; a1.z += v1.z * w1; a1.w += v1.w * w1;
        a2.x += v2.x * w2; a2.y += v2.y * w2; a2.z += v2.z * w2; a2.w += v2.w * w2;
    }

    // Inline overflow handling (tail is ~always 0; uniform branch).
    int tail = g_ovf_tail;
    if (tail > 0) {
        if (tail > OVFC) tail = OVFC;
        for (int e = 0; e < tail; e++) {
            if (g_ovf_dst[e] == node) {
                unsigned long long r = g_ovf_rec[e];
                unsigned s = (unsigned)(r & 0xffffffffu);
                float4 v = __ldg((const float4*)(xlane + ((size_t)(s << 8))));
                float wt = __uint_as_float((unsigned)(r >> 32));
                a0.x += v.x * wt; a0.y += v.y * wt;
                a0.z += v.z * wt; a0.w += v.w * wt;
            }
        }
    }

    float4 r;
    r.x = (a0.x + a1.x) + (a2.x + a3.x);
    r.y = (a0.y + a1.y) + (a2.y + a3.y);
    r.z = (a0.z + a1.z) + (a2.z + a3.z);
    r.w = (a0.w + a1.w) + (a2.w + a3.w);

    *(reinterpret_cast<float4*>(out + (size_t)node * D) + lane) = r;
}

extern "C" void kernel_launch(void* const* d_in, const int* in_sizes, int n_in,
                              void* d_out, int out_size) {
    const float* x   = (const float*)d_in[0];
    const void*  ei  = d_in[1];
    const float* w   = (const float*)d_in[2];
    float*       out = (float*)d_out;

    const int E = in_sizes[1] / 2;       // edge_index is (2, E)
    const int N = out_size / D;          // number of nodes

    // 1) init: zero counters (int4) + tail, probe dtype
    {
        int blocks = (MAXN / 4 + TPB - 1) / TPB;
        init_kernel<<<blocks, TPB>>>((const int*)ei, E);
    }
    // 2) bucket edges by dst
    {
        int blocks = (E + TPB - 1) / TPB;
        fill_kernel<<<blocks, TPB>>>(ei, w, E);
    }
    // 3) atomic-free gather/accumulate/store (handles overflow inline)
    {
        long long total = (long long)N * 16;
        int blocks = (int)((total + TPB - 1) / TPB);
        gather_kernel<<<blocks, TPB>>>(x, out, N);
    }
}